// round 10
// baseline (speedup 1.0000x reference)
#include <cuda_runtime.h>
#include <cuda_bf16.h>
#include <math.h>
#include <stdint.h>

// ---------------- problem sizes ----------------
#define NMS_N   256
#define HW      16384          // 128*128
#define WORDS   512            // 16384/32
#define NB      64             // batch for CRF
#define NPIX    (NB*HW)        // 1,048,576

// ---------------- persistent CRF config ----------------
#define CL      8              // cluster size (CTAs per image)
#define RPC     16             // rows per CTA
#define NTHR    512            // threads per CTA (16 rows x 32 col-groups)
#define W136    136            // padded row stride
#define PLS     ((RPC+2)*W136) // state plane: halo + RPC + halo = 18 rows
#define SMTOT   (2*PLS + 16)   // two state planes + 2x8 flag slots

// ---------------- device scratch (static, no allocation) ----------------
__device__ unsigned int g_packed[NMS_N * WORDS];   // [mask][word]
__device__ float        g_sums[NMS_N];
__device__ float        g_dmat[NMS_N * NMS_N];
__device__ float        g_comp[NMS_N];
__device__ int          g_cnt[NB];                 // count | (arrivals<<20)

// ================= helpers =================

__device__ __forceinline__ void cluster_sync_() {
    asm volatile("barrier.cluster.arrive.aligned;" ::: "memory");
    asm volatile("barrier.cluster.wait.aligned;" ::: "memory");
}

__device__ __forceinline__ void st_peer_f32(uint32_t local_addr, uint32_t peer_rank, float v) {
    uint32_t rem;
    asm volatile("mapa.shared::cluster.u32 %0, %1, %2;"
                 : "=r"(rem) : "r"(local_addr), "r"(peer_rank));
    asm volatile("st.shared::cluster.f32 [%0], %1;" :: "r"(rem), "f"(v) : "memory");
}

// ================= NMS =================

__global__ void pack_kernel(const float* __restrict__ seg) {
    int m   = blockIdx.x;
    int tid = threadIdx.x;         // 512 threads
    int warp = tid >> 5, lane = tid & 31;
    int cnt = 0;
    for (int w = warp; w < WORDS; w += 16) {
        float v = seg[(size_t)m * HW + w * 32 + lane];
        unsigned bal = __ballot_sync(0xffffffffu, v != 0.0f);
        if (lane == 0) {
            g_packed[m * WORDS + w] = bal;
            cnt += __popc(bal);
        }
    }
    __shared__ int scnt[16];
    if (lane == 0) scnt[warp] = cnt;
    __syncthreads();
    if (tid == 0) {
        int t = 0;
        for (int i = 0; i < 16; ++i) t += scnt[i];
        g_sums[m] = (float)t;
    }
}

__global__ void nms_iou_kernel(const int* __restrict__ labels) {
    int j = blockIdx.x;
    int i = threadIdx.x;
    __shared__ uint4 smj[WORDS / 4];
    if (i < WORDS / 4)
        smj[i] = ((const uint4*)(g_packed + (size_t)j * WORDS))[i];
    __syncthreads();

    float d = 0.0f;
    if (i < j && labels[i] == labels[j]) {
        const uint4* mi = (const uint4*)(g_packed + (size_t)i * WORDS);
        int inter = 0;
        #pragma unroll 8
        for (int w = 0; w < WORDS / 4; ++w) {
            uint4 a = mi[w];
            uint4 b = smj[w];
            inter += __popc(a.x & b.x) + __popc(a.y & b.y)
                   + __popc(a.z & b.z) + __popc(a.w & b.w);
        }
        float fi  = (float)inter;
        float uni = g_sums[j] + g_sums[i] - fi;
        d = fi / uni;
    }
    g_dmat[j * NMS_N + i] = d;

    __shared__ float red[NMS_N];
    red[i] = d;
    __syncthreads();
    for (int s = NMS_N / 2; s > 0; s >>= 1) {
        if (i < s) red[i] = fmaxf(red[i], red[i + s]);
        __syncthreads();
    }
    if (i == 0) g_comp[j] = red[0];
}

__global__ void nms_coef_kernel(const float* __restrict__ cate_scores,
                                float* __restrict__ out_scores) {
    int j = blockIdx.x;
    int i = threadIdx.x;
    float d  = g_dmat[j * NMS_N + i];
    float ci = g_comp[i];
    float v  = expf(-2.0f * d * d) / expf(-2.0f * ci * ci);
    __shared__ float red[NMS_N];
    red[i] = v;
    __syncthreads();
    for (int s = NMS_N / 2; s > 0; s >>= 1) {
        if (i < s) red[i] = fminf(red[i], red[i + s]);
        __syncthreads();
    }
    if (i == 0) out_scores[j] = cate_scores[j] * red[0];
}

// ================= persistent CRF (+ fused valid) =================
// Cluster of 8 CTAs per image, 16 rows each, 512 threads, 4 px/thread,
// 2 CTAs co-resident per SM. Weights register-resident; smem holds +-1 states.
// Each warp covers exactly one 128-col row -> edge states via shuffles.

__global__ void __cluster_dims__(CL, 1, 1) __launch_bounds__(NTHR, 2)
crf_persistent(const float* __restrict__ fm,
               const float* __restrict__ x, const float* __restrict__ tg,
               float* __restrict__ out_masks, float* __restrict__ out_valid) {
    __shared__ float sm[SMTOT];
    __shared__ int   red2[16];
    float* st0  = sm;
    float* st1  = sm + PLS;
    float* flag = sm + 2 * PLS;    // [parity*8 + rank]

    int t  = threadIdx.x;          // 512
    int b  = blockIdx.x >> 3;
    uint32_t r = blockIdx.x & 7;
    int tr   = t >> 5;             // 0..15 local row
    int lane = t & 31;
    int c    = lane << 2;          // 0..124 col base
    int gr = (int)r * RPC + tr;
    size_t gp = (size_t)b * HW + (size_t)gr * 128 + c;
    int so = (tr + 1) * W136 + 4 + c;

    for (int i = t; i < SMTOT; i += NTHR) sm[i] = 0.0f;

    if (r == 0 && t == 0) {        // reset per-image counter (graph replay safe)
        g_cnt[b] = 0;
        __threadfence();
    }

    // ---- weights in registers, grouped by stencil row ----
    float wN[4], wNW[4], wNE[4], wE[4], wW[4], wS[4], wSE[4], wSW[4];
    {
        const float* fb = fm + (size_t)b * 3 * HW;
        float sN[4], sNW[4], sNE[4], sE[4], sW[4], sS[4], sSE[4], sSW[4];
        #pragma unroll
        for (int ch = 0; ch < 3; ++ch) {
            const float* base = fb + (size_t)ch * HW;
            float w6[3][6];
            #pragma unroll
            for (int rr = 0; rr < 3; ++rr) {
                int row = gr - 1 + rr;
                bool rin = (row >= 0) && (row < 128);
                size_t rp = (size_t)(rin ? row : gr) * 128 + c;
                float4 v = *(const float4*)(base + rp);
                float lf = (c > 0)   ? base[rp - 1] : 0.0f;
                float rt = (c < 124) ? base[rp + 4] : 0.0f;
                if (!rin) { v = make_float4(0,0,0,0); lf = 0.0f; rt = 0.0f; }
                w6[rr][0] = lf  + 10.0f;
                w6[rr][1] = v.x + 10.0f;
                w6[rr][2] = v.y + 10.0f;
                w6[rr][3] = v.z + 10.0f;
                w6[rr][4] = v.w + 10.0f;
                w6[rr][5] = rt  + 10.0f;
            }
            #pragma unroll
            for (int j = 0; j < 4; ++j) {
                float cc = w6[1][1 + j];
                float dN  = w6[0][1 + j] - cc;
                float dNW = w6[0][j]     - cc;
                float dNE = w6[0][2 + j] - cc;
                float dE  = w6[1][2 + j] - cc;
                float dW  = w6[1][j]     - cc;
                float dS  = w6[2][1 + j] - cc;
                float dSE = w6[2][2 + j] - cc;
                float dSW = w6[2][j]     - cc;
                if (ch == 0) {
                    sN[j]=dN*dN; sNW[j]=dNW*dNW; sNE[j]=dNE*dNE;
                    sE[j]=dE*dE; sW[j]=dW*dW;
                    sS[j]=dS*dS; sSE[j]=dSE*dSE; sSW[j]=dSW*dSW;
                } else {
                    sN[j]=fmaf(dN,dN,sN[j]);    sNW[j]=fmaf(dNW,dNW,sNW[j]);
                    sNE[j]=fmaf(dNE,dNE,sNE[j]); sE[j]=fmaf(dE,dE,sE[j]);
                    sW[j]=fmaf(dW,dW,sW[j]);    sS[j]=fmaf(dS,dS,sS[j]);
                    sSE[j]=fmaf(dSE,dSE,sSE[j]); sSW[j]=fmaf(dSW,dSW,sSW[j]);
                }
            }
        }
        const float sp1 = 1.0f / 1800.0f;
        const float sp2 = 2.0f / 1800.0f;
        bool hT = (gr > 0), hB = (gr < 127);
        #pragma unroll
        for (int j = 0; j < 4; ++j) {
            int w = c + j;
            bool hL = (w > 0), hR = (w < 127);
            float ss, v;
            ss = sN[j];  v = 3.0f * expf(-ss * 2.0f - sp1); wN[j]  = hT        ? v : 0.0f;
            ss = sNW[j]; v = 3.0f * expf(-ss * 2.0f - sp2); wNW[j] = (hT && hL)? v : 0.0f;
            ss = sNE[j]; v = 3.0f * expf(-ss * 2.0f - sp2); wNE[j] = (hT && hR)? v : 0.0f;
            ss = sE[j];  v = 3.0f * expf(-ss * 2.0f - sp1); wE[j]  = hR        ? v : 0.0f;
            ss = sW[j];  v = 3.0f * expf(-ss * 2.0f - sp1); wW[j]  = hL        ? v : 0.0f;
            ss = sS[j];  v = 3.0f * expf(-ss * 2.0f - sp1); wS[j]  = hB        ? v : 0.0f;
            ss = sSE[j]; v = 3.0f * expf(-ss * 2.0f - sp2); wSE[j] = (hB && hR)? v : 0.0f;
            ss = sSW[j]; v = 3.0f * expf(-ss * 2.0f - sp2); wSW[j] = (hB && hL)? v : 0.0f;
        }
    }
    __syncthreads();   // smem zeroing complete before state writes

    // ---- init states (+-1) and target bits ----
    bool sndUp = (tr == 0)       && (r > 0);
    bool sndDn = (tr == RPC - 1) && (r < CL - 1);
    unsigned tb = 0, prevmask = 0;
    {
        float4 xa = *(const float4*)(x + gp);
        float4 ta = *(const float4*)(tg + gp);
        float xs[4] = {xa.x, xa.y, xa.z, xa.w};
        float ts[4] = {ta.x, ta.y, ta.z, ta.w};
        float sig[4];
        #pragma unroll
        for (int i = 0; i < 4; ++i) {
            if (ts[i] > 0.5f) tb |= (1u << i);
            bool on = (xs[i] * ts[i] > 0.5f);
            if (on) prevmask |= (1u << i);
            sig[i] = on ? 1.0f : -1.0f;
        }
        *(float4*)(st0 + so) = make_float4(sig[0], sig[1], sig[2], sig[3]);
        if (sndUp) {
            uint32_t la = (uint32_t)__cvta_generic_to_shared(st0 + (RPC + 1) * W136 + 4 + c);
            #pragma unroll
            for (int i = 0; i < 4; ++i) st_peer_f32(la + 4u * i, r - 1u, sig[i]);
        }
        if (sndDn) {
            uint32_t la = (uint32_t)__cvta_generic_to_shared(st0 + 4 + c);
            #pragma unroll
            for (int i = 0; i < 4; ++i) st_peer_f32(la + 4u * i, r + 1u, sig[i]);
        }
    }
    uint32_t flag_base = (uint32_t)__cvta_generic_to_shared(flag);
    cluster_sync_();

    const float* A = st0;
    float* B = st1;
    unsigned newmask = prevmask;
    for (int it = 0; it < 10; ++it) {
        const float* Ar = A + so;
        float acc[4];
        {   // mid row: center + E + W  (edges via shuffle; lane0/31 pads are 0)
            float4 m4 = *(const float4*)(Ar);
            float lm = __shfl_up_sync(0xffffffffu, m4.w, 1);
            float rm = __shfl_down_sync(0xffffffffu, m4.x, 1);
            if (lane == 0)  lm = 0.0f;
            if (lane == 31) rm = 0.0f;
            float mw[6] = {lm, m4.x, m4.y, m4.z, m4.w, rm};
            #pragma unroll
            for (int j = 0; j < 4; ++j) {
                float a = 3.0f * mw[j + 1];
                a += wE[j] * mw[j + 2];
                a += wW[j] * mw[j];
                acc[j] = a;
            }
        }
        {   // top row: N + NW + NE
            float4 u4 = *(const float4*)(Ar - W136);
            float lu = __shfl_up_sync(0xffffffffu, u4.w, 1);
            float ru = __shfl_down_sync(0xffffffffu, u4.x, 1);
            if (lane == 0)  lu = 0.0f;
            if (lane == 31) ru = 0.0f;
            float tw[6] = {lu, u4.x, u4.y, u4.z, u4.w, ru};
            #pragma unroll
            for (int j = 0; j < 4; ++j) {
                float a = acc[j];
                a += wN[j]  * tw[j + 1];
                a += wNW[j] * tw[j];
                a += wNE[j] * tw[j + 2];
                acc[j] = a;
            }
        }
        {   // bottom row: S + SE + SW
            float4 d4 = *(const float4*)(Ar + W136);
            float ld = __shfl_up_sync(0xffffffffu, d4.w, 1);
            float rd = __shfl_down_sync(0xffffffffu, d4.x, 1);
            if (lane == 0)  ld = 0.0f;
            if (lane == 31) rd = 0.0f;
            float bw[6] = {ld, d4.x, d4.y, d4.z, d4.w, rd};
            #pragma unroll
            for (int j = 0; j < 4; ++j) {
                float a = acc[j];
                a += wS[j]  * bw[j + 1];
                a += wSE[j] * bw[j + 2];
                a += wSW[j] * bw[j];
                acc[j] = a;
            }
        }
        newmask = 0;
        #pragma unroll
        for (int j = 0; j < 4; ++j)
            if (acc[j] > 0.0f && ((tb >> j) & 1u)) newmask |= (1u << j);

        int changed = (newmask != prevmask) ? 1 : 0;
        prevmask = newmask;
        int blkchg = __syncthreads_or(changed);
        if (it == 9) break;

        float sig[4];
        #pragma unroll
        for (int i = 0; i < 4; ++i)
            sig[i] = ((newmask >> i) & 1u) ? 1.0f : -1.0f;
        *(float4*)(B + so) = make_float4(sig[0], sig[1], sig[2], sig[3]);
        if (sndUp) {
            uint32_t la = (uint32_t)__cvta_generic_to_shared(B + (RPC + 1) * W136 + 4 + c);
            #pragma unroll
            for (int i = 0; i < 4; ++i) st_peer_f32(la + 4u * i, r - 1u, sig[i]);
        }
        if (sndDn) {
            uint32_t la = (uint32_t)__cvta_generic_to_shared(B + 4 + c);
            #pragma unroll
            for (int i = 0; i < 4; ++i) st_peer_f32(la + 4u * i, r + 1u, sig[i]);
        }
        if (t == 0) {
            float fv = blkchg ? 1.0f : 0.0f;
            uint32_t slot = flag_base + 4u * ((unsigned)(it & 1) * 8u + r);
            #pragma unroll
            for (uint32_t rr = 0; rr < CL; ++rr) st_peer_f32(slot, rr, fv);
        }
        cluster_sync_();
        int p8 = (it & 1) * 8;
        bool anychg = false;
        #pragma unroll
        for (int k = 0; k < CL; ++k) anychg |= (flag[p8 + k] != 0.0f);
        if (!anychg) break;   // exact fixed point across the whole image
        const float* tmp = A; A = B; B = (float*)tmp;
    }

    // ---- final outputs ----
    float o[4];
    #pragma unroll
    for (int i = 0; i < 4; ++i) o[i] = ((newmask >> i) & 1u) ? 1.0f : 0.0f;
    *(float4*)(out_masks + gp) = make_float4(o[0], o[1], o[2], o[3]);

    // ---- fused valid ----
    unsigned p = __popc(newmask);
    #pragma unroll
    for (int off = 16; off; off >>= 1) p += __shfl_down_sync(0xffffffffu, p, off);
    if (lane == 0) red2[t >> 5] = (int)p;
    __syncthreads();
    if (t < 32) {
        int v = (t < 16) ? red2[t] : 0;
        #pragma unroll
        for (int off = 16; off; off >>= 1) v += __shfl_down_sync(0xffffffffu, v, off);
        if (t == 0) {
            int ret = atomicAdd(&g_cnt[b], v + (1 << 20));
            int tot = ret + v + (1 << 20);
            if ((tot >> 20) == CL) {
                float cfl = (float)(tot & 0xFFFFF);
                out_valid[b] = (cfl >= 16384.0f * 0.05f && cfl <= 16384.0f * 0.95f)
                               ? 1.0f : 0.0f;
            }
        }
    }
}

// ================= launch =================

extern "C" void kernel_launch(void* const* d_in, const int* in_sizes, int n_in,
                              void* d_out, int out_size) {
    const float* seg_masks   = (const float*)d_in[0];
    const float* cate_scores = (const float*)d_in[1];
    const float* feature_map = (const float*)d_in[2];
    const float* x           = (const float*)d_in[3];
    const float* targets     = (const float*)d_in[4];
    const int*   cate_labels = (const int*)d_in[5];

    float* out_scores = (float*)d_out;                  // [256]
    float* out_masks  = out_scores + NMS_N;             // [64*128*128]
    float* out_valid  = out_masks + NPIX;               // [64]

    static cudaStream_t s2 = nullptr;
    static cudaEvent_t evFork = nullptr, evJoin = nullptr;
    if (s2 == nullptr) {
        cudaStreamCreateWithFlags(&s2, cudaStreamNonBlocking);
        cudaEventCreateWithFlags(&evFork, cudaEventDisableTiming);
        cudaEventCreateWithFlags(&evJoin, cudaEventDisableTiming);
    }

    // ---- fork: NMS chain on s2, CRF on the main stream ----
    cudaEventRecord(evFork, 0);
    cudaStreamWaitEvent(s2, evFork, 0);

    pack_kernel<<<NMS_N, 512, 0, s2>>>(seg_masks);
    nms_iou_kernel<<<NMS_N, NMS_N, 0, s2>>>(cate_labels);
    nms_coef_kernel<<<NMS_N, NMS_N, 0, s2>>>(cate_scores, out_scores);
    cudaEventRecord(evJoin, s2);

    crf_persistent<<<CL * NB, NTHR>>>(feature_map, x, targets, out_masks, out_valid);

    // ---- join ----
    cudaStreamWaitEvent(0, evJoin, 0);
}

// round 11
// speedup vs baseline: 1.0331x; 1.0331x over previous
#include <cuda_runtime.h>
#include <cuda_bf16.h>
#include <math.h>
#include <stdint.h>

// ---------------- problem sizes ----------------
#define NMS_N   256
#define HW      16384          // 128*128
#define WORDS   512            // 16384/32
#define NB      64             // batch for CRF
#define NPIX    (NB*HW)        // 1,048,576

// ---------------- persistent CRF config ----------------
#define CL      4              // cluster size (CTAs per image)
#define RPC     32             // rows per CTA
#define NTHR    1024           // threads per CTA
#define W136    136            // padded row stride
#define PLS     ((RPC+2)*W136) // state plane: halo + RPC + halo
#define SMTOT   (2*PLS + 8)

// ---------------- device scratch (static, no allocation) ----------------
__device__ unsigned int g_packed[NMS_N * WORDS];   // [mask][word]
__device__ float        g_sums[NMS_N];
__device__ float        g_dmat[NMS_N * NMS_N];
__device__ float        g_comp[NMS_N];
__device__ int          g_cnt[NB];                 // count | (arrivals<<20)

// ================= helpers =================

__device__ __forceinline__ void cluster_sync_() {
    asm volatile("barrier.cluster.arrive.aligned;" ::: "memory");
    asm volatile("barrier.cluster.wait.aligned;" ::: "memory");
}

__device__ __forceinline__ void st_peer_f32(uint32_t local_addr, uint32_t peer_rank, float v) {
    uint32_t rem;
    asm volatile("mapa.shared::cluster.u32 %0, %1, %2;"
                 : "=r"(rem) : "r"(local_addr), "r"(peer_rank));
    asm volatile("st.shared::cluster.f32 [%0], %1;" :: "r"(rem), "f"(v) : "memory");
}

// ================= NMS =================

__global__ void pack_kernel(const float* __restrict__ seg) {
    int m   = blockIdx.x;
    int tid = threadIdx.x;         // 512 threads
    int warp = tid >> 5, lane = tid & 31;
    int cnt = 0;
    for (int w = warp; w < WORDS; w += 16) {
        float v = seg[(size_t)m * HW + w * 32 + lane];
        unsigned bal = __ballot_sync(0xffffffffu, v != 0.0f);
        if (lane == 0) {
            g_packed[m * WORDS + w] = bal;
            cnt += __popc(bal);
        }
    }
    __shared__ int scnt[16];
    if (lane == 0) scnt[warp] = cnt;
    __syncthreads();
    if (tid == 0) {
        int t = 0;
        for (int i = 0; i < 16; ++i) t += scnt[i];
        g_sums[m] = (float)t;
    }
}

__global__ void nms_iou_kernel(const int* __restrict__ labels) {
    int j = blockIdx.x;
    int i = threadIdx.x;
    __shared__ uint4 smj[WORDS / 4];
    if (i < WORDS / 4)
        smj[i] = ((const uint4*)(g_packed + (size_t)j * WORDS))[i];
    __syncthreads();

    float d = 0.0f;
    if (i < j && labels[i] == labels[j]) {
        const uint4* mi = (const uint4*)(g_packed + (size_t)i * WORDS);
        int inter = 0;
        #pragma unroll 8
        for (int w = 0; w < WORDS / 4; ++w) {
            uint4 a = mi[w];
            uint4 b = smj[w];
            inter += __popc(a.x & b.x) + __popc(a.y & b.y)
                   + __popc(a.z & b.z) + __popc(a.w & b.w);
        }
        float fi  = (float)inter;
        float uni = g_sums[j] + g_sums[i] - fi;
        d = fi / uni;
    }
    g_dmat[j * NMS_N + i] = d;

    __shared__ float red[NMS_N];
    red[i] = d;
    __syncthreads();
    for (int s = NMS_N / 2; s > 0; s >>= 1) {
        if (i < s) red[i] = fmaxf(red[i], red[i + s]);
        __syncthreads();
    }
    if (i == 0) g_comp[j] = red[0];
}

__global__ void nms_coef_kernel(const float* __restrict__ cate_scores,
                                float* __restrict__ out_scores) {
    int j = blockIdx.x;
    int i = threadIdx.x;
    float d  = g_dmat[j * NMS_N + i];
    float ci = g_comp[i];
    float v  = expf(-2.0f * d * d) / expf(-2.0f * ci * ci);
    __shared__ float red[NMS_N];
    red[i] = v;
    __syncthreads();
    for (int s = NMS_N / 2; s > 0; s >>= 1) {
        if (i < s) red[i] = fminf(red[i], red[i + s]);
        __syncthreads();
    }
    if (i == 0) out_scores[j] = cate_scores[j] * red[0];
}

// ================= persistent CRF (+ fused valid) =================
// Cluster of 4 CTAs per image, 32 rows each, 1024 threads, 4 px/thread.
// Weights register-resident; smem holds +-1 states.
// Per-row activity skipping: a row whose 3-row neighborhood didn't change
// in the previous transition is provably at its next value -> skip exactly.

__global__ void __cluster_dims__(CL, 1, 1) __launch_bounds__(NTHR, 1)
crf_persistent(const float* __restrict__ fm,
               const float* __restrict__ x, const float* __restrict__ tg,
               float* __restrict__ out_masks, float* __restrict__ out_valid) {
    __shared__ float sm[SMTOT];
    __shared__ int   red2[32];
    __shared__ float rfl[2][RPC + 2];   // per-row changed flags, parity buffered
    float* st0  = sm;
    float* st1  = sm + PLS;
    float* flag = sm + 2 * PLS;    // [parity*4 + rank]

    int t  = threadIdx.x;          // 1024
    int b  = blockIdx.x >> 2;
    uint32_t r = blockIdx.x & 3;
    int tr   = t >> 5;             // 0..31 local row (one warp per row)
    int lane = t & 31;
    int c    = lane << 2;          // 0..124 col base
    int gr = (int)r * RPC + tr;
    size_t gp = (size_t)b * HW + (size_t)gr * 128 + c;
    int so = (tr + 1) * W136 + 4 + c;

    for (int i = t; i < SMTOT; i += NTHR) sm[i] = 0.0f;
    if (t < RPC + 2) {
        rfl[0][t] = (t >= 1 && t <= RPC) ? 1.0f : 0.0f;
        rfl[1][t] = 0.0f;
    }

    if (r == 0 && t == 0) {        // reset per-image counter (graph replay safe)
        g_cnt[b] = 0;
        __threadfence();
    }

    // ---- weights in registers, grouped by stencil row ----
    float wN[4], wNW[4], wNE[4], wE[4], wW[4], wS[4], wSE[4], wSW[4];
    {
        const float* fb = fm + (size_t)b * 3 * HW;
        float sN[4], sNW[4], sNE[4], sE[4], sW[4], sS[4], sSE[4], sSW[4];
        #pragma unroll
        for (int ch = 0; ch < 3; ++ch) {
            const float* base = fb + (size_t)ch * HW;
            float w6[3][6];
            #pragma unroll
            for (int rr = 0; rr < 3; ++rr) {
                int row = gr - 1 + rr;
                bool rin = (row >= 0) && (row < 128);
                size_t rp = (size_t)(rin ? row : gr) * 128 + c;
                float4 v = *(const float4*)(base + rp);
                float lf = (c > 0)   ? base[rp - 1] : 0.0f;
                float rt = (c < 124) ? base[rp + 4] : 0.0f;
                if (!rin) { v = make_float4(0,0,0,0); lf = 0.0f; rt = 0.0f; }
                w6[rr][0] = lf  + 10.0f;
                w6[rr][1] = v.x + 10.0f;
                w6[rr][2] = v.y + 10.0f;
                w6[rr][3] = v.z + 10.0f;
                w6[rr][4] = v.w + 10.0f;
                w6[rr][5] = rt  + 10.0f;
            }
            #pragma unroll
            for (int j = 0; j < 4; ++j) {
                float cc = w6[1][1 + j];
                float dN  = w6[0][1 + j] - cc;
                float dNW = w6[0][j]     - cc;
                float dNE = w6[0][2 + j] - cc;
                float dE  = w6[1][2 + j] - cc;
                float dW  = w6[1][j]     - cc;
                float dS  = w6[2][1 + j] - cc;
                float dSE = w6[2][2 + j] - cc;
                float dSW = w6[2][j]     - cc;
                if (ch == 0) {
                    sN[j]=dN*dN; sNW[j]=dNW*dNW; sNE[j]=dNE*dNE;
                    sE[j]=dE*dE; sW[j]=dW*dW;
                    sS[j]=dS*dS; sSE[j]=dSE*dSE; sSW[j]=dSW*dSW;
                } else {
                    sN[j]=fmaf(dN,dN,sN[j]);    sNW[j]=fmaf(dNW,dNW,sNW[j]);
                    sNE[j]=fmaf(dNE,dNE,sNE[j]); sE[j]=fmaf(dE,dE,sE[j]);
                    sW[j]=fmaf(dW,dW,sW[j]);    sS[j]=fmaf(dS,dS,sS[j]);
                    sSE[j]=fmaf(dSE,dSE,sSE[j]); sSW[j]=fmaf(dSW,dSW,sSW[j]);
                }
            }
        }
        const float sp1 = 1.0f / 1800.0f;
        const float sp2 = 2.0f / 1800.0f;
        bool hT = (gr > 0), hB = (gr < 127);
        #pragma unroll
        for (int j = 0; j < 4; ++j) {
            int w = c + j;
            bool hL = (w > 0), hR = (w < 127);
            float ss, v;
            ss = sN[j];  v = 3.0f * expf(-ss * 2.0f - sp1); wN[j]  = hT        ? v : 0.0f;
            ss = sNW[j]; v = 3.0f * expf(-ss * 2.0f - sp2); wNW[j] = (hT && hL)? v : 0.0f;
            ss = sNE[j]; v = 3.0f * expf(-ss * 2.0f - sp2); wNE[j] = (hT && hR)? v : 0.0f;
            ss = sE[j];  v = 3.0f * expf(-ss * 2.0f - sp1); wE[j]  = hR        ? v : 0.0f;
            ss = sW[j];  v = 3.0f * expf(-ss * 2.0f - sp1); wW[j]  = hL        ? v : 0.0f;
            ss = sS[j];  v = 3.0f * expf(-ss * 2.0f - sp1); wS[j]  = hB        ? v : 0.0f;
            ss = sSE[j]; v = 3.0f * expf(-ss * 2.0f - sp2); wSE[j] = (hB && hR)? v : 0.0f;
            ss = sSW[j]; v = 3.0f * expf(-ss * 2.0f - sp2); wSW[j] = (hB && hL)? v : 0.0f;
        }
    }
    __syncthreads();   // smem zeroing + rfl init complete before state writes

    // ---- init states (+-1) and target bits ----
    bool sndUp = (tr == 0)       && (r > 0);
    bool sndDn = (tr == RPC - 1) && (r < CL - 1);
    unsigned tb = 0, prevmask = 0;
    {
        float4 xa = *(const float4*)(x + gp);
        float4 ta = *(const float4*)(tg + gp);
        float xs[4] = {xa.x, xa.y, xa.z, xa.w};
        float ts[4] = {ta.x, ta.y, ta.z, ta.w};
        float sig[4];
        #pragma unroll
        for (int i = 0; i < 4; ++i) {
            if (ts[i] > 0.5f) tb |= (1u << i);
            bool on = (xs[i] * ts[i] > 0.5f);
            if (on) prevmask |= (1u << i);
            sig[i] = on ? 1.0f : -1.0f;
        }
        *(float4*)(st0 + so) = make_float4(sig[0], sig[1], sig[2], sig[3]);
        if (sndUp) {
            uint32_t la = (uint32_t)__cvta_generic_to_shared(st0 + (RPC + 1) * W136 + 4 + c);
            #pragma unroll
            for (int i = 0; i < 4; ++i) st_peer_f32(la + 4u * i, r - 1u, sig[i]);
        }
        if (sndDn) {
            uint32_t la = (uint32_t)__cvta_generic_to_shared(st0 + 4 + c);
            #pragma unroll
            for (int i = 0; i < 4; ++i) st_peer_f32(la + 4u * i, r + 1u, sig[i]);
        }
    }
    uint32_t flag_base = (uint32_t)__cvta_generic_to_shared(flag);
    cluster_sync_();

    const float* A = st0;
    float* B = st1;
    unsigned newmask = prevmask;
    for (int it = 0; it < 10; ++it) {
        int p = it & 1;
        // row active iff its 3-row neighborhood changed in the last transition
        bool act = (rfl[p][tr] != 0.0f) || (rfl[p][tr + 1] != 0.0f) ||
                   (rfl[p][tr + 2] != 0.0f);

        unsigned nm = prevmask;
        if (act) {
            const float* Ar = A + so;
            float acc[4];
            {   // mid row: center + E + W
                float4 m4 = *(const float4*)(Ar);
                float lm = Ar[-1], rm = Ar[4];
                float mw[6] = {lm, m4.x, m4.y, m4.z, m4.w, rm};
                #pragma unroll
                for (int j = 0; j < 4; ++j) {
                    float a = 3.0f * mw[j + 1];
                    a += wE[j] * mw[j + 2];
                    a += wW[j] * mw[j];
                    acc[j] = a;
                }
            }
            {   // top row: N + NW + NE
                float4 u4 = *(const float4*)(Ar - W136);
                float lu = Ar[-W136 - 1], ru = Ar[-W136 + 4];
                float tw[6] = {lu, u4.x, u4.y, u4.z, u4.w, ru};
                #pragma unroll
                for (int j = 0; j < 4; ++j) {
                    float a = acc[j];
                    a += wN[j]  * tw[j + 1];
                    a += wNW[j] * tw[j];
                    a += wNE[j] * tw[j + 2];
                    acc[j] = a;
                }
            }
            {   // bottom row: S + SE + SW
                float4 d4 = *(const float4*)(Ar + W136);
                float ld = Ar[W136 - 1], rd = Ar[W136 + 4];
                float bw[6] = {ld, d4.x, d4.y, d4.z, d4.w, rd};
                #pragma unroll
                for (int j = 0; j < 4; ++j) {
                    float a = acc[j];
                    a += wS[j]  * bw[j + 1];
                    a += wSE[j] * bw[j + 2];
                    a += wSW[j] * bw[j];
                    acc[j] = a;
                }
            }
            nm = 0;
            #pragma unroll
            for (int j = 0; j < 4; ++j)
                if (acc[j] > 0.0f && ((tb >> j) & 1u)) nm |= (1u << j);
        }
        newmask = nm;
        int changed = (nm != prevmask) ? 1 : 0;
        prevmask = nm;

        // per-row changed flag for next iteration (own + peer halo slots)
        unsigned wchg = __ballot_sync(0xffffffffu, changed);
        float fchg = wchg ? 1.0f : 0.0f;
        if (lane == 0) {
            rfl[p ^ 1][tr + 1] = fchg;
            if (tr == 0 && r > 0)
                st_peer_f32((uint32_t)__cvta_generic_to_shared(&rfl[p ^ 1][RPC + 1]),
                            r - 1u, fchg);
            if (tr == RPC - 1 && r < CL - 1)
                st_peer_f32((uint32_t)__cvta_generic_to_shared(&rfl[p ^ 1][0]),
                            r + 1u, fchg);
        }

        int blkchg = __syncthreads_or(changed);
        if (it == 9) break;

        if (act) {   // skipped rows: write buffer already holds the correct state
            float sig[4];
            #pragma unroll
            for (int i = 0; i < 4; ++i)
                sig[i] = ((nm >> i) & 1u) ? 1.0f : -1.0f;
            *(float4*)(B + so) = make_float4(sig[0], sig[1], sig[2], sig[3]);
            if (sndUp) {
                uint32_t la = (uint32_t)__cvta_generic_to_shared(B + (RPC + 1) * W136 + 4 + c);
                #pragma unroll
                for (int i = 0; i < 4; ++i) st_peer_f32(la + 4u * i, r - 1u, sig[i]);
            }
            if (sndDn) {
                uint32_t la = (uint32_t)__cvta_generic_to_shared(B + 4 + c);
                #pragma unroll
                for (int i = 0; i < 4; ++i) st_peer_f32(la + 4u * i, r + 1u, sig[i]);
            }
        }
        if (t == 0) {
            float fv = blkchg ? 1.0f : 0.0f;
            uint32_t slot = flag_base + 4u * ((unsigned)p * 4u + r);
            #pragma unroll
            for (uint32_t rr = 0; rr < CL; ++rr) st_peer_f32(slot, rr, fv);
        }
        cluster_sync_();
        int p4 = p * 4;
        bool anychg = (flag[p4] != 0.0f) || (flag[p4 + 1] != 0.0f) ||
                      (flag[p4 + 2] != 0.0f) || (flag[p4 + 3] != 0.0f);
        if (!anychg) break;   // exact fixed point across the whole image
        const float* tmp = A; A = B; B = (float*)tmp;
    }

    // ---- final outputs ----
    float o[4];
    #pragma unroll
    for (int i = 0; i < 4; ++i) o[i] = ((newmask >> i) & 1u) ? 1.0f : 0.0f;
    *(float4*)(out_masks + gp) = make_float4(o[0], o[1], o[2], o[3]);

    // ---- fused valid ----
    unsigned p = __popc(newmask);
    #pragma unroll
    for (int off = 16; off; off >>= 1) p += __shfl_down_sync(0xffffffffu, p, off);
    if (lane == 0) red2[t >> 5] = (int)p;
    __syncthreads();
    if (t < 32) {
        int v = red2[t];
        #pragma unroll
        for (int off = 16; off; off >>= 1) v += __shfl_down_sync(0xffffffffu, v, off);
        if (t == 0) {
            int ret = atomicAdd(&g_cnt[b], v + (1 << 20));
            int tot = ret + v + (1 << 20);
            if ((tot >> 20) == CL) {
                float cfl = (float)(tot & 0xFFFFF);
                out_valid[b] = (cfl >= 16384.0f * 0.05f && cfl <= 16384.0f * 0.95f)
                               ? 1.0f : 0.0f;
            }
        }
    }
}

// ================= launch =================

extern "C" void kernel_launch(void* const* d_in, const int* in_sizes, int n_in,
                              void* d_out, int out_size) {
    const float* seg_masks   = (const float*)d_in[0];
    const float* cate_scores = (const float*)d_in[1];
    const float* feature_map = (const float*)d_in[2];
    const float* x           = (const float*)d_in[3];
    const float* targets     = (const float*)d_in[4];
    const int*   cate_labels = (const int*)d_in[5];

    float* out_scores = (float*)d_out;                  // [256]
    float* out_masks  = out_scores + NMS_N;             // [64*128*128]
    float* out_valid  = out_masks + NPIX;               // [64]

    static cudaStream_t s2 = nullptr;
    static cudaEvent_t evFork = nullptr, evJoin = nullptr;
    if (s2 == nullptr) {
        cudaStreamCreateWithFlags(&s2, cudaStreamNonBlocking);
        cudaEventCreateWithFlags(&evFork, cudaEventDisableTiming);
        cudaEventCreateWithFlags(&evJoin, cudaEventDisableTiming);
    }

    // ---- fork: NMS chain on s2, CRF on the main stream ----
    cudaEventRecord(evFork, 0);
    cudaStreamWaitEvent(s2, evFork, 0);

    pack_kernel<<<NMS_N, 512, 0, s2>>>(seg_masks);
    nms_iou_kernel<<<NMS_N, NMS_N, 0, s2>>>(cate_labels);
    nms_coef_kernel<<<NMS_N, NMS_N, 0, s2>>>(cate_scores, out_scores);
    cudaEventRecord(evJoin, s2);

    crf_persistent<<<CL * NB, NTHR>>>(feature_map, x, targets, out_masks, out_valid);

    // ---- join ----
    cudaStreamWaitEvent(0, evJoin, 0);
}

// round 12
// speedup vs baseline: 1.1453x; 1.1086x over previous
#include <cuda_runtime.h>
#include <cuda_bf16.h>
#include <math.h>
#include <stdint.h>

// ---------------- problem sizes ----------------
#define NMS_N   256
#define HW      16384          // 128*128
#define WORDS   512            // 16384/32
#define NB      64             // batch for CRF
#define NPIX    (NB*HW)        // 1,048,576

// ---------------- persistent CRF config ----------------
#define CL      4              // cluster size (CTAs per image)
#define RPC     32             // rows per CTA
#define NTHR    1024           // threads per CTA
#define W136    136            // padded row stride
#define PLS     ((RPC+2)*W136) // state plane: halo + RPC + halo
#define SMTOT   (2*PLS)

// ---------------- device scratch (static, no allocation) ----------------
__device__ unsigned int g_packed[NMS_N * WORDS];   // [mask][word]
__device__ float        g_sums[NMS_N];
__device__ float        g_dmat[NMS_N * NMS_N];
__device__ float        g_comp[NMS_N];
__device__ int          g_cnt[NB];                 // count | (arrivals<<20)

// ================= helpers =================

__device__ __forceinline__ void cluster_sync_() {
    asm volatile("barrier.cluster.arrive.aligned;" ::: "memory");
    asm volatile("barrier.cluster.wait.aligned;" ::: "memory");
}

__device__ __forceinline__ void st_peer_f32(uint32_t local_addr, uint32_t peer_rank, float v) {
    uint32_t rem;
    asm volatile("mapa.shared::cluster.u32 %0, %1, %2;"
                 : "=r"(rem) : "r"(local_addr), "r"(peer_rank));
    asm volatile("st.shared::cluster.f32 [%0], %1;" :: "r"(rem), "f"(v) : "memory");
}

// ================= NMS =================

__global__ void pack_kernel(const float* __restrict__ seg) {
    int m   = blockIdx.x;
    int tid = threadIdx.x;         // 512 threads
    int warp = tid >> 5, lane = tid & 31;
    int cnt = 0;
    for (int w = warp; w < WORDS; w += 16) {
        float v = seg[(size_t)m * HW + w * 32 + lane];
        unsigned bal = __ballot_sync(0xffffffffu, v != 0.0f);
        if (lane == 0) {
            g_packed[m * WORDS + w] = bal;
            cnt += __popc(bal);
        }
    }
    __shared__ int scnt[16];
    if (lane == 0) scnt[warp] = cnt;
    __syncthreads();
    if (tid == 0) {
        int t = 0;
        for (int i = 0; i < 16; ++i) t += scnt[i];
        g_sums[m] = (float)t;
    }
}

__global__ void nms_iou_kernel(const int* __restrict__ labels) {
    int j = blockIdx.x;
    int i = threadIdx.x;
    __shared__ uint4 smj[WORDS / 4];
    if (i < WORDS / 4)
        smj[i] = ((const uint4*)(g_packed + (size_t)j * WORDS))[i];
    __syncthreads();

    float d = 0.0f;
    if (i < j && labels[i] == labels[j]) {
        const uint4* mi = (const uint4*)(g_packed + (size_t)i * WORDS);
        int inter = 0;
        #pragma unroll 8
        for (int w = 0; w < WORDS / 4; ++w) {
            uint4 a = mi[w];
            uint4 b = smj[w];
            inter += __popc(a.x & b.x) + __popc(a.y & b.y)
                   + __popc(a.z & b.z) + __popc(a.w & b.w);
        }
        float fi  = (float)inter;
        float uni = g_sums[j] + g_sums[i] - fi;
        d = fi / uni;
    }
    g_dmat[j * NMS_N + i] = d;

    __shared__ float red[NMS_N];
    red[i] = d;
    __syncthreads();
    for (int s = NMS_N / 2; s > 0; s >>= 1) {
        if (i < s) red[i] = fmaxf(red[i], red[i + s]);
        __syncthreads();
    }
    if (i == 0) g_comp[j] = red[0];
}

__global__ void nms_coef_kernel(const float* __restrict__ cate_scores,
                                float* __restrict__ out_scores) {
    int j = blockIdx.x;
    int i = threadIdx.x;
    float d  = g_dmat[j * NMS_N + i];
    float ci = g_comp[i];
    float v  = expf(-2.0f * d * d) / expf(-2.0f * ci * ci);
    __shared__ float red[NMS_N];
    red[i] = v;
    __syncthreads();
    for (int s = NMS_N / 2; s > 0; s >>= 1) {
        if (i < s) red[i] = fminf(red[i], red[i + s]);
        __syncthreads();
    }
    if (i == 0) out_scores[j] = cate_scores[j] * red[0];
}

// ================= persistent CRF (+ fused valid) =================
// Cluster of 4 CTAs per image, 32 rows each, 1024 threads, 4 px/thread.
// Weights register-resident; smem holds +-1 states. Fixed 10 iterations,
// exactly ONE cluster barrier per iteration (release/acquire orders smem).

__global__ void __cluster_dims__(CL, 1, 1) __launch_bounds__(NTHR, 1)
crf_persistent(const float* __restrict__ fm,
               const float* __restrict__ x, const float* __restrict__ tg,
               float* __restrict__ out_masks, float* __restrict__ out_valid) {
    __shared__ float sm[SMTOT];
    __shared__ int   red2[32];
    float* st0  = sm;
    float* st1  = sm + PLS;

    int t  = threadIdx.x;          // 1024
    int b  = blockIdx.x >> 2;
    uint32_t r = blockIdx.x & 3;
    int tr   = t >> 5;             // 0..31 local row (one warp per row)
    int lane = t & 31;
    int c    = lane << 2;          // 0..124 col base
    int gr = (int)r * RPC + tr;
    size_t gp = (size_t)b * HW + (size_t)gr * 128 + c;
    int so = (tr + 1) * W136 + 4 + c;

    for (int i = t; i < SMTOT; i += NTHR) sm[i] = 0.0f;

    if (r == 0 && t == 0) {        // reset per-image counter (graph replay safe)
        g_cnt[b] = 0;
        __threadfence();
    }

    // ---- weights in registers, grouped by stencil row ----
    // wW[j] for j>=1 equals wE[j-1] (same pixel pair, identical expression).
    float wN[4], wNW[4], wNE[4], wE[4], wW0, wS[4], wSE[4], wSW[4];
    {
        const float* fb = fm + (size_t)b * 3 * HW;
        float sN[4], sNW[4], sNE[4], sE[4], sW0, sS[4], sSE[4], sSW[4];
        #pragma unroll
        for (int ch = 0; ch < 3; ++ch) {
            const float* base = fb + (size_t)ch * HW;
            float w6[3][6];
            #pragma unroll
            for (int rr = 0; rr < 3; ++rr) {
                int row = gr - 1 + rr;
                bool rin = (row >= 0) && (row < 128);
                size_t rp = (size_t)(rin ? row : gr) * 128 + c;
                float4 v = *(const float4*)(base + rp);
                float lf = (c > 0)   ? base[rp - 1] : 0.0f;
                float rt = (c < 124) ? base[rp + 4] : 0.0f;
                if (!rin) { v = make_float4(0,0,0,0); lf = 0.0f; rt = 0.0f; }
                w6[rr][0] = lf  + 10.0f;
                w6[rr][1] = v.x + 10.0f;
                w6[rr][2] = v.y + 10.0f;
                w6[rr][3] = v.z + 10.0f;
                w6[rr][4] = v.w + 10.0f;
                w6[rr][5] = rt  + 10.0f;
            }
            {   // W weight of px0 only (pair with left-neighbor pixel)
                float dW = w6[1][0] - w6[1][1];
                if (ch == 0) sW0 = dW * dW; else sW0 = fmaf(dW, dW, sW0);
            }
            #pragma unroll
            for (int j = 0; j < 4; ++j) {
                float cc = w6[1][1 + j];
                float dN  = w6[0][1 + j] - cc;
                float dNW = w6[0][j]     - cc;
                float dNE = w6[0][2 + j] - cc;
                float dE  = w6[1][2 + j] - cc;
                float dS  = w6[2][1 + j] - cc;
                float dSE = w6[2][2 + j] - cc;
                float dSW = w6[2][j]     - cc;
                if (ch == 0) {
                    sN[j]=dN*dN; sNW[j]=dNW*dNW; sNE[j]=dNE*dNE;
                    sE[j]=dE*dE;
                    sS[j]=dS*dS; sSE[j]=dSE*dSE; sSW[j]=dSW*dSW;
                } else {
                    sN[j]=fmaf(dN,dN,sN[j]);    sNW[j]=fmaf(dNW,dNW,sNW[j]);
                    sNE[j]=fmaf(dNE,dNE,sNE[j]); sE[j]=fmaf(dE,dE,sE[j]);
                    sS[j]=fmaf(dS,dS,sS[j]);
                    sSE[j]=fmaf(dSE,dSE,sSE[j]); sSW[j]=fmaf(dSW,dSW,sSW[j]);
                }
            }
        }
        const float sp1 = 1.0f / 1800.0f;
        const float sp2 = 2.0f / 1800.0f;
        bool hT = (gr > 0), hB = (gr < 127);
        #pragma unroll
        for (int j = 0; j < 4; ++j) {
            int w = c + j;
            bool hL = (w > 0), hR = (w < 127);
            float ss, v;
            ss = sN[j];  v = 3.0f * expf(-ss * 2.0f - sp1); wN[j]  = hT        ? v : 0.0f;
            ss = sNW[j]; v = 3.0f * expf(-ss * 2.0f - sp2); wNW[j] = (hT && hL)? v : 0.0f;
            ss = sNE[j]; v = 3.0f * expf(-ss * 2.0f - sp2); wNE[j] = (hT && hR)? v : 0.0f;
            ss = sE[j];  v = 3.0f * expf(-ss * 2.0f - sp1); wE[j]  = hR        ? v : 0.0f;
            ss = sS[j];  v = 3.0f * expf(-ss * 2.0f - sp1); wS[j]  = hB        ? v : 0.0f;
            ss = sSE[j]; v = 3.0f * expf(-ss * 2.0f - sp2); wSE[j] = (hB && hR)? v : 0.0f;
            ss = sSW[j]; v = 3.0f * expf(-ss * 2.0f - sp2); wSW[j] = (hB && hL)? v : 0.0f;
        }
        {
            float v = 3.0f * expf(-sW0 * 2.0f - sp1);
            wW0 = (c > 0) ? v : 0.0f;
        }
    }
    __syncthreads();   // smem zeroing complete before state writes

    // ---- init states (+-1) and target bits ----
    bool sndUp = (tr == 0)       && (r > 0);
    bool sndDn = (tr == RPC - 1) && (r < CL - 1);
    unsigned tb = 0, curmask = 0;
    {
        float4 xa = *(const float4*)(x + gp);
        float4 ta = *(const float4*)(tg + gp);
        float xs[4] = {xa.x, xa.y, xa.z, xa.w};
        float ts[4] = {ta.x, ta.y, ta.z, ta.w};
        float sig[4];
        #pragma unroll
        for (int i = 0; i < 4; ++i) {
            if (ts[i] > 0.5f) tb |= (1u << i);
            bool on = (xs[i] * ts[i] > 0.5f);
            if (on) curmask |= (1u << i);
            sig[i] = on ? 1.0f : -1.0f;
        }
        *(float4*)(st0 + so) = make_float4(sig[0], sig[1], sig[2], sig[3]);
        if (sndUp) {
            uint32_t la = (uint32_t)__cvta_generic_to_shared(st0 + (RPC + 1) * W136 + 4 + c);
            #pragma unroll
            for (int i = 0; i < 4; ++i) st_peer_f32(la + 4u * i, r - 1u, sig[i]);
        }
        if (sndDn) {
            uint32_t la = (uint32_t)__cvta_generic_to_shared(st0 + 4 + c);
            #pragma unroll
            for (int i = 0; i < 4; ++i) st_peer_f32(la + 4u * i, r + 1u, sig[i]);
        }
    }
    cluster_sync_();

    const float* A = st0;
    float* B = st1;
    for (int it = 0; it < 10; ++it) {
        const float* Ar = A + so;
        float acc[4];
        {   // mid row: center + E + W  (wW[j] == wE[j-1] for j>=1)
            float4 m4 = *(const float4*)(Ar);
            float lm = Ar[-1], rm = Ar[4];
            float mw[6] = {lm, m4.x, m4.y, m4.z, m4.w, rm};
            #pragma unroll
            for (int j = 0; j < 4; ++j) {
                float wWj = (j == 0) ? wW0 : wE[j - 1];
                float a = 3.0f * mw[j + 1];
                a += wE[j] * mw[j + 2];
                a += wWj   * mw[j];
                acc[j] = a;
            }
        }
        {   // top row: N + NW + NE
            float4 u4 = *(const float4*)(Ar - W136);
            float lu = Ar[-W136 - 1], ru = Ar[-W136 + 4];
            float tw[6] = {lu, u4.x, u4.y, u4.z, u4.w, ru};
            #pragma unroll
            for (int j = 0; j < 4; ++j) {
                float a = acc[j];
                a += wN[j]  * tw[j + 1];
                a += wNW[j] * tw[j];
                a += wNE[j] * tw[j + 2];
                acc[j] = a;
            }
        }
        {   // bottom row: S + SE + SW
            float4 d4 = *(const float4*)(Ar + W136);
            float ld = Ar[W136 - 1], rd = Ar[W136 + 4];
            float bw[6] = {ld, d4.x, d4.y, d4.z, d4.w, rd};
            #pragma unroll
            for (int j = 0; j < 4; ++j) {
                float a = acc[j];
                a += wS[j]  * bw[j + 1];
                a += wSE[j] * bw[j + 2];
                a += wSW[j] * bw[j];
                acc[j] = a;
            }
        }
        unsigned nm = 0;
        #pragma unroll
        for (int j = 0; j < 4; ++j)
            if (acc[j] > 0.0f && ((tb >> j) & 1u)) nm |= (1u << j);
        curmask = nm;
        if (it == 9) break;

        float sig[4];
        #pragma unroll
        for (int i = 0; i < 4; ++i)
            sig[i] = ((nm >> i) & 1u) ? 1.0f : -1.0f;
        *(float4*)(B + so) = make_float4(sig[0], sig[1], sig[2], sig[3]);
        if (sndUp) {
            uint32_t la = (uint32_t)__cvta_generic_to_shared(B + (RPC + 1) * W136 + 4 + c);
            #pragma unroll
            for (int i = 0; i < 4; ++i) st_peer_f32(la + 4u * i, r - 1u, sig[i]);
        }
        if (sndDn) {
            uint32_t la = (uint32_t)__cvta_generic_to_shared(B + 4 + c);
            #pragma unroll
            for (int i = 0; i < 4; ++i) st_peer_f32(la + 4u * i, r + 1u, sig[i]);
        }
        cluster_sync_();   // release/acquire: orders all smem writes cluster-wide
        const float* tmp = A; A = B; B = (float*)tmp;
    }

    // ---- final outputs ----
    float o[4];
    #pragma unroll
    for (int i = 0; i < 4; ++i) o[i] = ((curmask >> i) & 1u) ? 1.0f : 0.0f;
    *(float4*)(out_masks + gp) = make_float4(o[0], o[1], o[2], o[3]);

    // ---- fused valid ----
    unsigned p = __popc(curmask);
    #pragma unroll
    for (int off = 16; off; off >>= 1) p += __shfl_down_sync(0xffffffffu, p, off);
    if (lane == 0) red2[t >> 5] = (int)p;
    __syncthreads();
    if (t < 32) {
        int v = red2[t];
        #pragma unroll
        for (int off = 16; off; off >>= 1) v += __shfl_down_sync(0xffffffffu, v, off);
        if (t == 0) {
            int ret = atomicAdd(&g_cnt[b], v + (1 << 20));
            int tot = ret + v + (1 << 20);
            if ((tot >> 20) == CL) {
                float cfl = (float)(tot & 0xFFFFF);
                out_valid[b] = (cfl >= 16384.0f * 0.05f && cfl <= 16384.0f * 0.95f)
                               ? 1.0f : 0.0f;
            }
        }
    }
}

// ================= launch =================

extern "C" void kernel_launch(void* const* d_in, const int* in_sizes, int n_in,
                              void* d_out, int out_size) {
    const float* seg_masks   = (const float*)d_in[0];
    const float* cate_scores = (const float*)d_in[1];
    const float* feature_map = (const float*)d_in[2];
    const float* x           = (const float*)d_in[3];
    const float* targets     = (const float*)d_in[4];
    const int*   cate_labels = (const int*)d_in[5];

    float* out_scores = (float*)d_out;                  // [256]
    float* out_masks  = out_scores + NMS_N;             // [64*128*128]
    float* out_valid  = out_masks + NPIX;               // [64]

    static cudaStream_t s2 = nullptr;
    static cudaEvent_t evFork = nullptr, evJoin = nullptr;
    if (s2 == nullptr) {
        cudaStreamCreateWithFlags(&s2, cudaStreamNonBlocking);
        cudaEventCreateWithFlags(&evFork, cudaEventDisableTiming);
        cudaEventCreateWithFlags(&evJoin, cudaEventDisableTiming);
    }

    // ---- fork: NMS chain on s2, CRF on the main stream ----
    cudaEventRecord(evFork, 0);
    cudaStreamWaitEvent(s2, evFork, 0);

    pack_kernel<<<NMS_N, 512, 0, s2>>>(seg_masks);
    nms_iou_kernel<<<NMS_N, NMS_N, 0, s2>>>(cate_labels);
    nms_coef_kernel<<<NMS_N, NMS_N, 0, s2>>>(cate_scores, out_scores);
    cudaEventRecord(evJoin, s2);

    crf_persistent<<<CL * NB, NTHR>>>(feature_map, x, targets, out_masks, out_valid);

    // ---- join ----
    cudaStreamWaitEvent(0, evJoin, 0);
}